// round 16
// baseline (speedup 1.0000x reference)
#include <cuda_runtime.h>
#include <cstdint>

// Beam hypotheses update — fused scatter kernel, per-thread ALU meta with
// streamed board compares (no v[9] register array -> lower reg pressure).
// Block (j, b) reads items row j (loads front-issued at cycle 0), computes
// rank of slot j in the post-insert board via 8 streamed compares (board row
// is 36B, L1-resident after the first warp), scatters the row (int32 -> fp32
// via magic-number add). No smem, no barrier, no shfl.
// Output (f32, concat): len[B], worst[B], board[B,9], items[B,9,G].

#define NSLOT 9

// exact for 0 <= x < 2^23
static __device__ __forceinline__ float u2f_fast(int x) {
    return __int_as_float(x | 0x4B000000) - 8388608.0f;
}

template <int VPT>
__global__ __launch_bounds__(128) void bh_scatter_stream(
    const int*   __restrict__ hyp,        // [B, hyp_w]
    const float* __restrict__ slp,        // [B]
    const int*   __restrict__ lnst,       // [B]
    const float* __restrict__ worst_in,   // [B]
    const float* __restrict__ board_in,   // [B, 9]
    const int*   __restrict__ items_in,   // [B, 9, G]
    const int*   __restrict__ curlen_ptr, // scalar (may be null)
    float*       __restrict__ out,
    int batch, int hyp_w, int gen_len)
{
    const int j   = blockIdx.x;           // SOURCE slot 0..8
    const int b   = blockIdx.y;           // batch row
    const int tid = threadIdx.x;

    // ---- front-batched source loads: address independent of meta ----
    const int4* src_row = reinterpret_cast<const int4*>(
        items_in + ((size_t)b * NSLOT + j) * gen_len);
    int4 a[VPT];
#pragma unroll
    for (int it = 0; it < VPT; it++)
        a[it] = __ldcs(&src_row[tid + it * 128]);

    // ---- meta (redundant per thread; streamed compares) ----
    const int cur_len   = curlen_ptr ? __ldg(curlen_ptr) : hyp_w;
    const int num_beams = NSLOT - 1;

    const float score = __ldg(&slp[b]) / (float)cur_len;   // length_penalty=1
    const int   ln    = __ldg(&lnst[b]);
    const float worst = __ldg(&worst_in[b]);
    const bool  cond  = (ln < num_beams) || (score > worst);
    const int   new_len = ln + 1;
    const int   ins_idx = (new_len > NSLOT) ? 0 : num_beams;

    const float* brow = board_in + (size_t)b * NSLOT;

    const float binj = __ldg(&brow[j]);
    const float vj   = (j == ins_idx) ? score : binj;

    // rank of element j under stable (value, index) ascending order
    int r = 0;
#pragma unroll
    for (int k = 0; k < NSLOT; k++) {
        if (k != j) {
            const float vk = (k == ins_idx) ? score : __ldg(&brow[k]);
            r += ((vk < vj) || (vk == vj && k < j)) ? 1 : 0;
        }
    }

    const int  dest    = cond ? r : j;
    const bool use_hyp = cond && (j == ins_idx);

    // ---- scalar outputs ----
    if (tid == 0) {
        out[(size_t)2 * batch + (size_t)b * NSLOT + dest] = cond ? vj : binj;
        if (j == 0) {
            // two smallest of v by (value, index), streamed
            float m1 = 3.402823466e+38f; int m1i = -1;
#pragma unroll
            for (int i = 0; i < NSLOT; i++) {
                const float vi = (i == ins_idx) ? score : __ldg(&brow[i]);
                if (vi < m1) { m1 = vi; m1i = i; }
            }
            float m2 = 3.402823466e+38f;
#pragma unroll
            for (int i = 0; i < NSLOT; i++) {
                if (i != m1i) {
                    const float vi = (i == ins_idx) ? score : __ldg(&brow[i]);
                    m2 = fminf(m2, vi);
                }
            }
            const float new_worst =
                (new_len > num_beams) ? m2 : fminf(worst, score);
            out[b]         = (float)(cond ? new_len : ln);
            out[batch + b] = cond ? new_worst : worst;
        }
    }

    // ---- hyp overlay (only the replaced source row; first cur_len elems) ----
    if (use_hyp) {
        const int* h = hyp + (size_t)b * hyp_w;
        if ((cur_len & 3) == 0 && (hyp_w & 3) == 0) {
            const int4* hyp_row = reinterpret_cast<const int4*>(h);
            const int cvec = cur_len >> 2;
#pragma unroll
            for (int it = 0; it < VPT; it++) {
                int vix = tid + it * 128;
                if (vix < cvec) a[it] = __ldg(&hyp_row[vix]);
            }
        } else {
#pragma unroll
            for (int it = 0; it < VPT; it++) {
                int base = (tid + it * 128) << 2;
                if (base + 0 < cur_len) a[it].x = h[base + 0];
                if (base + 1 < cur_len) a[it].y = h[base + 1];
                if (base + 2 < cur_len) a[it].z = h[base + 2];
                if (base + 3 < cur_len) a[it].w = h[base + 3];
            }
        }
    }

    // ---- convert (magic-number, full-rate) + scatter stores ----
    float4* dst_row = reinterpret_cast<float4*>(
        out + (size_t)batch * (2 + NSLOT) +
        ((size_t)b * NSLOT + dest) * gen_len);
#pragma unroll
    for (int it = 0; it < VPT; it++) {
        float4 f;
        f.x = u2f_fast(a[it].x); f.y = u2f_fast(a[it].y);
        f.z = u2f_fast(a[it].z); f.w = u2f_fast(a[it].w);
        __stcs(&dst_row[tid + it * 128], f);
    }
}

// ---------------- generic fallback (arbitrary gen_len) ---------------------
__global__ __launch_bounds__(128) void bh_scatter_generic(
    const int*   __restrict__ hyp,
    const float* __restrict__ slp,
    const int*   __restrict__ lnst,
    const float* __restrict__ worst_in,
    const float* __restrict__ board_in,
    const int*   __restrict__ items_in,
    const int*   __restrict__ curlen_ptr,
    float*       __restrict__ out,
    int batch, int hyp_w, int gen_len)
{
    const int j   = blockIdx.x;
    const int b   = blockIdx.y;
    const int tid = threadIdx.x;

    const int cur_len   = curlen_ptr ? __ldg(curlen_ptr) : hyp_w;
    const int num_beams = NSLOT - 1;

    const float score = __ldg(&slp[b]) / (float)cur_len;
    const int   ln    = __ldg(&lnst[b]);
    const float worst = __ldg(&worst_in[b]);
    const bool  cond  = (ln < num_beams) || (score > worst);
    const int   new_len = ln + 1;
    const int   ins_idx = (new_len > NSLOT) ? 0 : num_beams;

    const float* brow = board_in + (size_t)b * NSLOT;
    const float binj = __ldg(&brow[j]);
    const float vj   = (j == ins_idx) ? score : binj;

    int r = 0;
#pragma unroll
    for (int k = 0; k < NSLOT; k++) {
        if (k != j) {
            const float vk = (k == ins_idx) ? score : __ldg(&brow[k]);
            r += ((vk < vj) || (vk == vj && k < j)) ? 1 : 0;
        }
    }

    const int  dest    = cond ? r : j;
    const bool use_hyp = cond && (j == ins_idx);

    if (tid == 0) {
        out[(size_t)2 * batch + (size_t)b * NSLOT + dest] = cond ? vj : binj;
        if (j == 0) {
            float m1 = 3.402823466e+38f; int m1i = -1;
#pragma unroll
            for (int i = 0; i < NSLOT; i++) {
                const float vi = (i == ins_idx) ? score : __ldg(&brow[i]);
                if (vi < m1) { m1 = vi; m1i = i; }
            }
            float m2 = 3.402823466e+38f;
#pragma unroll
            for (int i = 0; i < NSLOT; i++) {
                if (i != m1i) {
                    const float vi = (i == ins_idx) ? score : __ldg(&brow[i]);
                    m2 = fminf(m2, vi);
                }
            }
            const float new_worst =
                (new_len > num_beams) ? m2 : fminf(worst, score);
            out[b]         = (float)(cond ? new_len : ln);
            out[batch + b] = cond ? new_worst : worst;
        }
    }

    const int* src_row = items_in + ((size_t)b * NSLOT + j) * gen_len;
    float*     dst_row = out + (size_t)batch * (2 + NSLOT) +
                         ((size_t)b * NSLOT + dest) * gen_len;
    const int* h = hyp + (size_t)b * hyp_w;

    for (int e = tid; e < gen_len; e += 128) {
        int val = (use_hyp && e < cur_len) ? h[e] : __ldcs(&src_row[e]);
        __stcs(&dst_row[e], (float)val);
    }
}

extern "C" void kernel_launch(void* const* d_in, const int* in_sizes, int n_in,
                              void* d_out, int out_size)
{
    const int*   hyp    = (const int*)  d_in[0];
    const float* slp    = (const float*)d_in[1];
    const int*   lnst   = (const int*)  d_in[2];
    const float* worst  = (const float*)d_in[3];
    const float* board  = (const float*)d_in[4];
    const int*   items  = (const int*)  d_in[5];
    const int*   curlen = (n_in > 6) ? (const int*)d_in[6] : nullptr;

    const int batch   = in_sizes[1];
    const int hyp_w   = in_sizes[0] / batch;
    const int gen_len = in_sizes[5] / (batch * NSLOT);
    float* out = (float*)d_out;

    dim3 grid(NSLOT, batch);
    if (gen_len == 2048) {
        bh_scatter_stream<4><<<grid, 128>>>(
            hyp, slp, lnst, worst, board, items, curlen, out,
            batch, hyp_w, gen_len);
    } else {
        bh_scatter_generic<<<grid, 128>>>(
            hyp, slp, lnst, worst, board, items, curlen, out,
            batch, hyp_w, gen_len);
    }
}

// round 17
// speedup vs baseline: 1.0055x; 1.0055x over previous
#include <cuda_runtime.h>
#include <cstdint>

// Beam hypotheses update — single fused SCATTER kernel (round-5 structure).
// Block (j, b) reads items row j (address known at cycle 0 -> loads front-issued,
// overlapped with meta), computes the rank of slot j in the post-insert board
// with plain ALU compares (no shfl/ballot -> no MIO-pipe dependency), and
// scatters the row (int32 -> fp32 via magic-number add, full-rate) to its
// destination rank. No smem, no barrier.
// Output (f32, concat): len[B], worst[B], board[B,9], items[B,9,G].

#define NSLOT 9

// exact for 0 <= x < 2^23
__device__ __forceinline__ float u2f_fast(int x) {
    return __int_as_float(x | 0x4B000000) - 8388608.0f;
}

template <int VPT>
__global__ __launch_bounds__(128) void beam_scatter_kernel(
    const int*   __restrict__ hyp,        // [B, hyp_w]
    const float* __restrict__ slp,        // [B]
    const int*   __restrict__ lnst,       // [B]
    const float* __restrict__ worst_in,   // [B]
    const float* __restrict__ board_in,   // [B, 9]
    const int*   __restrict__ items_in,   // [B, 9, G]
    const int*   __restrict__ curlen_ptr, // scalar (may be null)
    float*       __restrict__ out,
    int batch, int hyp_w, int gen_len)
{
    const int j   = blockIdx.x;           // SOURCE slot 0..8
    const int b   = blockIdx.y;           // batch row
    const int tid = threadIdx.x;

    // ---- front-batched source loads: address independent of meta ----
    const int4* src_row = reinterpret_cast<const int4*>(
        items_in + ((size_t)b * NSLOT + j) * gen_len);
    int4 a[VPT];
#pragma unroll
    for (int it = 0; it < VPT; it++)
        a[it] = __ldcs(&src_row[tid + it * 128]);

    // ---- meta (redundant per thread; ALU-only rank, no sort) ----
    const int cur_len   = curlen_ptr ? __ldg(curlen_ptr) : hyp_w;
    const int num_beams = NSLOT - 1;

    const float score = __ldg(&slp[b]) / (float)cur_len;   // length_penalty=1
    const int   ln    = __ldg(&lnst[b]);
    const float worst = __ldg(&worst_in[b]);
    const bool  cond  = (ln < num_beams) || (score > worst);
    const int   new_len = ln + 1;
    const int   ins_idx = (new_len > NSLOT) ? 0 : num_beams;

    float v[NSLOT];
    float binj = 0.f;
#pragma unroll
    for (int i = 0; i < NSLOT; i++) {
        v[i] = __ldg(&board_in[(size_t)b * NSLOT + i]);
        if (i == j) binj = v[i];
    }
#pragma unroll
    for (int i = 0; i < NSLOT; i++)
        if (i == ins_idx) v[i] = score;

    // rank of element j under stable (value, index) ascending order
    int r = 0;
#pragma unroll
    for (int k = 0; k < NSLOT; k++)
        if (k != j)
            r += ((v[k] < v[j]) || (v[k] == v[j] && k < j)) ? 1 : 0;

    const int  dest    = cond ? r : j;
    const bool use_hyp = cond && (j == ins_idx);

    // ---- scalar outputs ----
    if (tid == 0) {
        out[(size_t)2 * batch + (size_t)b * NSLOT + dest] = cond ? v[j] : binj;
        if (j == 0) {
            // second smallest by (value, index)
            float m1 = v[0]; int m1i = 0;
#pragma unroll
            for (int i = 1; i < NSLOT; i++)
                if (v[i] < m1) { m1 = v[i]; m1i = i; }
            float m2 = 3.402823466e+38f;
#pragma unroll
            for (int i = 0; i < NSLOT; i++)
                if (i != m1i) m2 = fminf(m2, v[i]);
            const float new_worst =
                (new_len > num_beams) ? m2 : fminf(worst, score);
            out[b]         = (float)(cond ? new_len : ln);
            out[batch + b] = cond ? new_worst : worst;
        }
    }

    // ---- hyp overlay (only the replaced source row; first cur_len elems) ----
    if (use_hyp) {
        const int* h = hyp + (size_t)b * hyp_w;
        if ((cur_len & 3) == 0 && (hyp_w & 3) == 0) {
            const int4* hyp_row = reinterpret_cast<const int4*>(h);
            const int cvec = cur_len >> 2;
#pragma unroll
            for (int it = 0; it < VPT; it++) {
                int vix = tid + it * 128;
                if (vix < cvec) a[it] = __ldg(&hyp_row[vix]);
            }
        } else {
#pragma unroll
            for (int it = 0; it < VPT; it++) {
                int base = (tid + it * 128) << 2;
                if (base + 0 < cur_len) a[it].x = h[base + 0];
                if (base + 1 < cur_len) a[it].y = h[base + 1];
                if (base + 2 < cur_len) a[it].z = h[base + 2];
                if (base + 3 < cur_len) a[it].w = h[base + 3];
            }
        }
    }

    // ---- convert (magic-number, full-rate) + scatter stores ----
    float4* dst_row = reinterpret_cast<float4*>(
        out + (size_t)batch * (2 + NSLOT) +
        ((size_t)b * NSLOT + dest) * gen_len);
#pragma unroll
    for (int it = 0; it < VPT; it++) {
        float4 f;
        f.x = u2f_fast(a[it].x); f.y = u2f_fast(a[it].y);
        f.z = u2f_fast(a[it].z); f.w = u2f_fast(a[it].w);
        __stcs(&dst_row[tid + it * 128], f);
    }
}

// ---------------- generic fallback (arbitrary gen_len) ---------------------
__global__ __launch_bounds__(128) void beam_scatter_kernel_gen(
    const int*   __restrict__ hyp,
    const float* __restrict__ slp,
    const int*   __restrict__ lnst,
    const float* __restrict__ worst_in,
    const float* __restrict__ board_in,
    const int*   __restrict__ items_in,
    const int*   __restrict__ curlen_ptr,
    float*       __restrict__ out,
    int batch, int hyp_w, int gen_len)
{
    const int j   = blockIdx.x;
    const int b   = blockIdx.y;
    const int tid = threadIdx.x;

    const int cur_len   = curlen_ptr ? __ldg(curlen_ptr) : hyp_w;
    const int num_beams = NSLOT - 1;

    const float score = __ldg(&slp[b]) / (float)cur_len;
    const int   ln    = __ldg(&lnst[b]);
    const float worst = __ldg(&worst_in[b]);
    const bool  cond  = (ln < num_beams) || (score > worst);
    const int   new_len = ln + 1;
    const int   ins_idx = (new_len > NSLOT) ? 0 : num_beams;

    float v[NSLOT];
    float binj = 0.f;
#pragma unroll
    for (int i = 0; i < NSLOT; i++) {
        v[i] = __ldg(&board_in[(size_t)b * NSLOT + i]);
        if (i == j) binj = v[i];
    }
#pragma unroll
    for (int i = 0; i < NSLOT; i++)
        if (i == ins_idx) v[i] = score;

    int r = 0;
#pragma unroll
    for (int k = 0; k < NSLOT; k++)
        if (k != j)
            r += ((v[k] < v[j]) || (v[k] == v[j] && k < j)) ? 1 : 0;

    const int  dest    = cond ? r : j;
    const bool use_hyp = cond && (j == ins_idx);

    if (tid == 0) {
        out[(size_t)2 * batch + (size_t)b * NSLOT + dest] = cond ? v[j] : binj;
        if (j == 0) {
            float m1 = v[0]; int m1i = 0;
#pragma unroll
            for (int i = 1; i < NSLOT; i++)
                if (v[i] < m1) { m1 = v[i]; m1i = i; }
            float m2 = 3.402823466e+38f;
#pragma unroll
            for (int i = 0; i < NSLOT; i++)
                if (i != m1i) m2 = fminf(m2, v[i]);
            const float new_worst =
                (new_len > num_beams) ? m2 : fminf(worst, score);
            out[b]         = (float)(cond ? new_len : ln);
            out[batch + b] = cond ? new_worst : worst;
        }
    }

    const int* src_row = items_in + ((size_t)b * NSLOT + j) * gen_len;
    float*     dst_row = out + (size_t)batch * (2 + NSLOT) +
                         ((size_t)b * NSLOT + dest) * gen_len;
    const int* h = hyp + (size_t)b * hyp_w;

    for (int e = tid; e < gen_len; e += 128) {
        int val = (use_hyp && e < cur_len) ? h[e] : __ldcs(&src_row[e]);
        __stcs(&dst_row[e], (float)val);
    }
}

extern "C" void kernel_launch(void* const* d_in, const int* in_sizes, int n_in,
                              void* d_out, int out_size)
{
    const int*   hyp    = (const int*)  d_in[0];
    const float* slp    = (const float*)d_in[1];
    const int*   lnst   = (const int*)  d_in[2];
    const float* worst  = (const float*)d_in[3];
    const float* board  = (const float*)d_in[4];
    const int*   items  = (const int*)  d_in[5];
    const int*   curlen = (n_in > 6) ? (const int*)d_in[6] : nullptr;

    const int batch   = in_sizes[1];
    const int hyp_w   = in_sizes[0] / batch;
    const int gen_len = in_sizes[5] / (batch * NSLOT);
    float* out = (float*)d_out;

    dim3 grid(NSLOT, batch);
    if (gen_len == 2048) {
        beam_scatter_kernel<4><<<grid, 128>>>(
            hyp, slp, lnst, worst, board, items, curlen, out,
            batch, hyp_w, gen_len);
    } else {
        beam_scatter_kernel_gen<<<grid, 128>>>(
            hyp, slp, lnst, worst, board, items, curlen, out,
            batch, hyp_w, gen_len);
    }
}